// round 15
// baseline (speedup 1.0000x reference)
#include <cuda_runtime.h>
#include <cuda_bf16.h>
#include <cstdint>

// Greedy CTC decode, single fused kernel, NO synchronization (FINAL, R9/R13):
//   emission: [T, V=128] fp32
//   out (fp32, 3*T): [ idx(0:T) | keep(T:2T) | path_score(2T:3T) ]
//
// Each warp owns 8 consecutive rows and additionally loads row base-1 (the
// neighboring warp's last row -> L1/L2-deduped: ~27MB extra DRAM on 524MB
// compulsory, measured). 9 front-batched LDG.128 (MLP=9). Per-row warp
// argmax uses 2 REDUX collectives: max over monotone key, then min over
// tied lanes' column indices (= first occurrence, exactly matching
// jnp.argmax). Dedup runs inline with the carried prev; lane 0 stores
// idx/keep/score as float4s.
//
// MEASURED OPTIMUM — do not "improve":
//   44 regs -> 5 CTAs/SM (occ ~52%) beat every higher-occupancy variant
//   (occ 60.6% -> +2.3us, occ 82.5% -> +1.8us): more resident CTAs deepen
//   cross-CTA L1tex-queue contention for this front-batched load pattern.
//   Replays of this binary: 82.18 / 82.66 / 82.43 us; kernel 79.9-81.0 us,
//   86.7-86.9% DRAM-active, 6.87-6.89 TB/s.

#define V 128
#define BLANK 0
#define WARPS_PER_BLOCK 8
#define ROWS_PER_WARP 8
#define ROWS_PER_BLOCK (WARPS_PER_BLOCK * ROWS_PER_WARP)   // 64
#define FULL_MASK 0xFFFFFFFFu

// Order-preserving fp32 bits -> u32 map and inverse.
__device__ __forceinline__ unsigned fmono(float f) {
    unsigned b = __float_as_uint(f);
    return b ^ ((unsigned)((int)b >> 31) | 0x80000000u);
}
__device__ __forceinline__ float funmono(unsigned u) {
    unsigned b = u ^ ((unsigned)((int)(~u) >> 31) | 0x80000000u);
    return __uint_as_float(b);
}

// Warp argmax of one row held as lane-local float4. Uniform result on all lanes.
__device__ __forceinline__ void warp_row_argmax(const float4 v, int lane,
                                                float& o_idx, float& o_max)
{
    float best = v.x; int bi = lane * 4;
    if (v.y > best) { best = v.y; bi = lane * 4 + 1; }
    if (v.z > best) { best = v.z; bi = lane * 4 + 2; }
    if (v.w > best) { best = v.w; bi = lane * 4 + 3; }

    unsigned key  = fmono(best);
    unsigned wmax = __reduce_max_sync(FULL_MASK, key);
    unsigned cand = (key == wmax) ? (unsigned)bi : 0x7FFFFFFFu;
    unsigned widx = __reduce_min_sync(FULL_MASK, cand);  // lowest col of ties

    o_idx = (float)widx;
    o_max = funmono(wmax);
}

__global__ void __launch_bounds__(WARPS_PER_BLOCK * 32)
ctc_fused_kernel(const float* __restrict__ em,
                 float* __restrict__ out_idx,
                 float* __restrict__ out_keep,
                 float* __restrict__ out_score)
{
    const int lane = threadIdx.x & 31;
    const int base = (blockIdx.x * WARPS_PER_BLOCK + (threadIdx.x >> 5)) * ROWS_PER_WARP;

    // Front-batched loads: 8 tile rows + 1 prev row, all independent (MLP=9).
    float4 v[ROWS_PER_WARP];
    #pragma unroll
    for (int k = 0; k < ROWS_PER_WARP; k++) {
        v[k] = reinterpret_cast<const float4*>(em + (size_t)(base + k) * V)[lane];
    }
    float4 pv;
    const bool has_prev = (base > 0);
    if (has_prev) {
        // Last row of the preceding warp's tile: L1/L2-deduplicated fetch.
        pv = reinterpret_cast<const float4*>(em + (size_t)(base - 1) * V)[lane];
    }

    // prev symbol for row 0 of this tile.
    float prev = -1.0f;
    if (has_prev) {
        float pi, pm;
        warp_row_argmax(pv, lane, pi, pm);
        prev = pi;
    }

    float res_idx[ROWS_PER_WARP], kp[ROWS_PER_WARP], sc[ROWS_PER_WARP];

    #pragma unroll
    for (int k = 0; k < ROWS_PER_WARP; k++) {
        float ci, cm;
        warp_row_argmax(v[k], lane, ci, cm);
        bool keep = (ci != prev) && (ci != (float)BLANK);
        res_idx[k] = ci;
        kp[k] = keep ? 1.0f : 0.0f;
        sc[k] = keep ? cm : 0.0f;
        prev = ci;
    }

    if (lane == 0) {
        // base is a multiple of 8 -> 16B-aligned float4 stores
        reinterpret_cast<float4*>(out_idx + base)[0] =
            make_float4(res_idx[0], res_idx[1], res_idx[2], res_idx[3]);
        reinterpret_cast<float4*>(out_idx + base)[1] =
            make_float4(res_idx[4], res_idx[5], res_idx[6], res_idx[7]);
        reinterpret_cast<float4*>(out_keep + base)[0] =
            make_float4(kp[0], kp[1], kp[2], kp[3]);
        reinterpret_cast<float4*>(out_keep + base)[1] =
            make_float4(kp[4], kp[5], kp[6], kp[7]);
        reinterpret_cast<float4*>(out_score + base)[0] =
            make_float4(sc[0], sc[1], sc[2], sc[3]);
        reinterpret_cast<float4*>(out_score + base)[1] =
            make_float4(sc[4], sc[5], sc[6], sc[7]);
    }
}

extern "C" void kernel_launch(void* const* d_in, const int* in_sizes, int n_in,
                              void* d_out, int out_size)
{
    const float* em = (const float*)d_in[0];
    float* out = (float*)d_out;

    const int rows = in_sizes[0] / V;            // T = 1048576 (divisible by 64)
    float* out_idx   = out;                      // [0:T)
    float* out_keep  = out + rows;               // [T:2T)
    float* out_score = out + 2 * (size_t)rows;   // [2T:3T)

    dim3 block(WARPS_PER_BLOCK * 32);            // 256
    dim3 grid(rows / ROWS_PER_BLOCK);            // exact: 16384
    ctc_fused_kernel<<<grid, block>>>(em, out_idx, out_keep, out_score);
}

// round 16
// speedup vs baseline: 1.0078x; 1.0078x over previous
#include <cuda_runtime.h>
#include <cuda_bf16.h>
#include <cstdint>

// Greedy CTC decode, single fused kernel, NO synchronization (FINAL, R9/R13):
//   emission: [T, V=128] fp32
//   out (fp32, 3*T): [ idx(0:T) | keep(T:2T) | path_score(2T:3T) ]
//
// Each warp owns 8 consecutive rows and additionally loads row base-1 (the
// neighboring warp's last row -> L1/L2-deduped: ~27MB extra DRAM on 524MB
// compulsory, measured). 9 front-batched LDG.128 (MLP=9). Per-row warp
// argmax uses 2 REDUX collectives: max over monotone key, then min over
// tied lanes' column indices (= first occurrence, exactly matching
// jnp.argmax). Dedup runs inline with the carried prev; lane 0 stores
// idx/keep/score as float4s.
//
// MEASURED OPTIMUM — do not "improve":
//   44 regs -> 5 CTAs/SM (occ ~52%) beat every higher-occupancy variant
//   (occ 60.6% -> +2.3us, occ 82.5% -> +1.8us): more resident CTAs deepen
//   cross-CTA L1tex-queue contention for this front-batched load pattern.
//   Replays of this binary: 82.18 / 82.66 / 82.43 / 82.66 us; kernel
//   79.9-80.4 us, 86.4-86.9% DRAM-active, 6.85-6.89 TB/s.
//   Ruled out on evidence: PDL (neutral), persistence (-4us), occupancy
//   up/down (-1.8/-2.3us), __stcs (neutral), packed single-REDUX
//   (correctness-unsafe), TMA (LTS-cap path-independent).

#define V 128
#define BLANK 0
#define WARPS_PER_BLOCK 8
#define ROWS_PER_WARP 8
#define ROWS_PER_BLOCK (WARPS_PER_BLOCK * ROWS_PER_WARP)   // 64
#define FULL_MASK 0xFFFFFFFFu

// Order-preserving fp32 bits -> u32 map and inverse.
__device__ __forceinline__ unsigned fmono(float f) {
    unsigned b = __float_as_uint(f);
    return b ^ ((unsigned)((int)b >> 31) | 0x80000000u);
}
__device__ __forceinline__ float funmono(unsigned u) {
    unsigned b = u ^ ((unsigned)((int)(~u) >> 31) | 0x80000000u);
    return __uint_as_float(b);
}

// Warp argmax of one row held as lane-local float4. Uniform result on all lanes.
__device__ __forceinline__ void warp_row_argmax(const float4 v, int lane,
                                                float& o_idx, float& o_max)
{
    float best = v.x; int bi = lane * 4;
    if (v.y > best) { best = v.y; bi = lane * 4 + 1; }
    if (v.z > best) { best = v.z; bi = lane * 4 + 2; }
    if (v.w > best) { best = v.w; bi = lane * 4 + 3; }

    unsigned key  = fmono(best);
    unsigned wmax = __reduce_max_sync(FULL_MASK, key);
    unsigned cand = (key == wmax) ? (unsigned)bi : 0x7FFFFFFFu;
    unsigned widx = __reduce_min_sync(FULL_MASK, cand);  // lowest col of ties

    o_idx = (float)widx;
    o_max = funmono(wmax);
}

__global__ void __launch_bounds__(WARPS_PER_BLOCK * 32)
ctc_fused_kernel(const float* __restrict__ em,
                 float* __restrict__ out_idx,
                 float* __restrict__ out_keep,
                 float* __restrict__ out_score)
{
    const int lane = threadIdx.x & 31;
    const int base = (blockIdx.x * WARPS_PER_BLOCK + (threadIdx.x >> 5)) * ROWS_PER_WARP;

    // Front-batched loads: 8 tile rows + 1 prev row, all independent (MLP=9).
    float4 v[ROWS_PER_WARP];
    #pragma unroll
    for (int k = 0; k < ROWS_PER_WARP; k++) {
        v[k] = reinterpret_cast<const float4*>(em + (size_t)(base + k) * V)[lane];
    }
    float4 pv;
    const bool has_prev = (base > 0);
    if (has_prev) {
        // Last row of the preceding warp's tile: L1/L2-deduplicated fetch.
        pv = reinterpret_cast<const float4*>(em + (size_t)(base - 1) * V)[lane];
    }

    // prev symbol for row 0 of this tile.
    float prev = -1.0f;
    if (has_prev) {
        float pi, pm;
        warp_row_argmax(pv, lane, pi, pm);
        prev = pi;
    }

    float res_idx[ROWS_PER_WARP], kp[ROWS_PER_WARP], sc[ROWS_PER_WARP];

    #pragma unroll
    for (int k = 0; k < ROWS_PER_WARP; k++) {
        float ci, cm;
        warp_row_argmax(v[k], lane, ci, cm);
        bool keep = (ci != prev) && (ci != (float)BLANK);
        res_idx[k] = ci;
        kp[k] = keep ? 1.0f : 0.0f;
        sc[k] = keep ? cm : 0.0f;
        prev = ci;
    }

    if (lane == 0) {
        // base is a multiple of 8 -> 16B-aligned float4 stores
        reinterpret_cast<float4*>(out_idx + base)[0] =
            make_float4(res_idx[0], res_idx[1], res_idx[2], res_idx[3]);
        reinterpret_cast<float4*>(out_idx + base)[1] =
            make_float4(res_idx[4], res_idx[5], res_idx[6], res_idx[7]);
        reinterpret_cast<float4*>(out_keep + base)[0] =
            make_float4(kp[0], kp[1], kp[2], kp[3]);
        reinterpret_cast<float4*>(out_keep + base)[1] =
            make_float4(kp[4], kp[5], kp[6], kp[7]);
        reinterpret_cast<float4*>(out_score + base)[0] =
            make_float4(sc[0], sc[1], sc[2], sc[3]);
        reinterpret_cast<float4*>(out_score + base)[1] =
            make_float4(sc[4], sc[5], sc[6], sc[7]);
    }
}

extern "C" void kernel_launch(void* const* d_in, const int* in_sizes, int n_in,
                              void* d_out, int out_size)
{
    const float* em = (const float*)d_in[0];
    float* out = (float*)d_out;

    const int rows = in_sizes[0] / V;            // T = 1048576 (divisible by 64)
    float* out_idx   = out;                      // [0:T)
    float* out_keep  = out + rows;               // [T:2T)
    float* out_score = out + 2 * (size_t)rows;   // [2T:3T)

    dim3 block(WARPS_PER_BLOCK * 32);            // 256
    dim3 grid(rows / ROWS_PER_BLOCK);            // exact: 16384
    ctc_fused_kernel<<<grid, block>>>(em, out_idx, out_keep, out_score);
}